// round 5
// baseline (speedup 1.0000x reference)
#include <cuda_runtime.h>

namespace {
constexpr int H = 128, Wd = 128;
constexpr int PLANE = H * Wd;          // 16384
constexpr int HALF = 64;               // rows per CTA
constexpr int NBLOCKS = 32 * 64 * 2;   // 4096 half-plane CTAs (6.9 waves @4/SM)
constexpr int RPW = HALF / 8;          // 8 rows per warp
}

struct RowS {
    float x[6];   // [0]=left edge, [1..4]=own 4 cols, [5]=right edge
    int   b[6];   // bins
};

__device__ __forceinline__ float4 ldrow(const float* __restrict__ xp, int r,
                                        int lane) {
    float4 v = make_float4(0.f, 0.f, 0.f, 0.f);
    if ((unsigned)r < (unsigned)H)
        v = __ldg(reinterpret_cast<const float4*>(xp + r * Wd + lane * 4));
    return v;
}

__device__ __forceinline__ int quant(float x) {
    return (int)fminf(x * 5.0f, 4.0f);          // x>=0; floor==trunc
}

// Quantize + edge exchange. Only x is shuffled (2 MIO ops); edge bins are
// recomputed locally on the fma pipe (MIO is the binding resource).
__device__ __forceinline__ void build(float4 v, int lane, RowS& R) {
    R.x[1] = v.x; R.x[2] = v.y; R.x[3] = v.z; R.x[4] = v.w;
#pragma unroll
    for (int i = 1; i <= 4; ++i) R.b[i] = quant(R.x[i]);
    R.x[0] = __shfl_up_sync(0xffffffffu, v.w, 1);
    R.x[5] = __shfl_down_sync(0xffffffffu, v.x, 1);
    if (lane == 0)  R.x[0] = 0.f;   // x=0 kills the term; b irrelevant
    if (lane == 31) R.x[5] = 0.f;
    R.b[0] = quant(R.x[0]);
    R.b[5] = quant(R.x[5]);
}

__global__ __launch_bounds__(256, 4)
void col_kernel(const float* __restrict__ x,
                const float* __restrict__ Wp,
                const float* __restrict__ Lp,
                float* __restrict__ out) {
    // LDS table for the 6 lower terms (dh=1,2): bank-replicated, lane l only
    // touches bank l. addr = laneBase + bp*128 + bq*640 + o6*3200.
    __shared__ float sWL[6 * 25 * 32];

    for (int t = threadIdx.x; t < 6 * 25 * 32; t += 256) {
        int idx = t >> 5;               // o6*25 + bq*5 + bp   (o6 = o-3)
        int o6 = idx / 25;
        int i  = idx - o6 * 25;
        sWL[t] = Wp[o6 + 3] * Lp[i];
    }

    // Shuffle tables for the 3 top-row terms (dh=0): lane l (l<25) holds
    // W[0][k] * L[l], l = bq*5 + bp.
    const int lane = threadIdx.x & 31;
    float lval = (lane < 25) ? __ldg(Lp + lane) : 0.f;
    const float WL0 = __ldg(Wp + 0) * lval;
    const float WL1 = __ldg(Wp + 1) * lval;
    const float WL2 = __ldg(Wp + 2) * lval;
    __syncthreads();

    const int plane = blockIdx.x >> 1;
    const int half  = blockIdx.x & 1;
    const float* xp = x + (size_t)plane * PLANE;
    float* op = out + (size_t)plane * PLANE;

    const int warp = threadIdx.x >> 5;
    const int r0 = half * HALF + warp * RPW;
    const char* laneBase = reinterpret_cast<const char*>(sWL) + lane * 4;

    RowS Rr[3];
    float4 wv[2];
    build(ldrow(xp, r0 - 1, lane), lane, Rr[0]);
    build(ldrow(xp, r0,     lane), lane, Rr[1]);
    wv[0] = ldrow(xp, r0 + 1, lane);

#pragma unroll
    for (int k = 0; k < RPW; ++k) {
        const int r = r0 + k;
        wv[(k + 1) & 1] = ldrow(xp, r + 2, lane);   // prefetch (OOB -> zeros)
        build(wv[k & 1], lane, Rr[(k + 2) % 3]);    // loaded last iteration

        const RowS& A  = Rr[k % 3];
        const RowS& Bc = Rr[(k + 1) % 3];
        const RowS& Cn = Rr[(k + 2) % 3];

        float res[4];
#pragma unroll
        for (int i = 0; i < 4; ++i) {
            const int bp = Bc.b[i + 1];

            // dh=0 row via shuffle-table gather
            float sA;
            {
                int l0 = A.b[i + 0] * 5 + bp;
                int l1 = A.b[i + 1] * 5 + bp;
                int l2 = A.b[i + 2] * 5 + bp;
                sA  = __shfl_sync(0xffffffffu, WL0, l0) * A.x[i + 0];
                sA += __shfl_sync(0xffffffffu, WL1, l1) * A.x[i + 1];
                sA += __shfl_sync(0xffffffffu, WL2, l2) * A.x[i + 2];
            }

            // dh=1,2 rows via replicated LDS table
            const char* pb = laneBase + bp * 128;
            float sL = 0.f;
#define COL_TERM(R, o6, dw)                                                    \
            sL += *reinterpret_cast<const float*>(                             \
                      pb + (R).b[i + (dw)] * 640 + (o6) * 3200)                \
                  * (R).x[i + (dw)];
            COL_TERM(Bc, 0, 0) COL_TERM(Bc, 1, 1) COL_TERM(Bc, 2, 2)
            COL_TERM(Cn, 3, 0) COL_TERM(Cn, 4, 1) COL_TERM(Cn, 5, 2)
#undef COL_TERM
            res[i] = sA + sL;
        }

        *reinterpret_cast<float4*>(op + r * Wd + lane * 4) =
            make_float4(res[0], res[1], res[2], res[3]);
    }
}

extern "C" void kernel_launch(void* const* d_in, const int* in_sizes, int n_in,
                              void* d_out, int out_size) {
    const float* x = nullptr;
    const float* W = nullptr;
    const float* L = nullptr;
    for (int i = 0; i < n_in; ++i) {
        if (in_sizes[i] == 9)       W = (const float*)d_in[i];
        else if (in_sizes[i] == 25) L = (const float*)d_in[i];
        else                        x = (const float*)d_in[i];
    }
    col_kernel<<<NBLOCKS, 256>>>(x, W, L, (float*)d_out);
}

// round 6
// speedup vs baseline: 1.1271x; 1.1271x over previous
#include <cuda_runtime.h>

namespace {
constexpr int H = 128, Wd = 128;
constexpr int PLANE = H * Wd;                       // 16384
constexpr int NPLANES = 32 * 64;                    // 2048
constexpr long long TOTROWS = (long long)NPLANES * H;  // 262144
constexpr int NBLK = 608;                           // ~4 CTAs/SM
constexpr int NWARP = NBLK * 8;                     // 4864 warp strips
}

struct RowS {
    float x[6];   // [0]=left edge, [1..4]=own 4 cols, [5]=right edge
    int   b[6];   // bins
};

__device__ __forceinline__ float4 ldrow(const float* __restrict__ xp, int r,
                                        int lane) {
    float4 v = make_float4(0.f, 0.f, 0.f, 0.f);
    if ((unsigned)r < (unsigned)H)
        v = __ldg(reinterpret_cast<const float4*>(xp + r * Wd + lane * 4));
    return v;
}

__device__ __forceinline__ int quant(float x) {
    return (int)fminf(x * 5.0f, 4.0f);          // x>=0; floor==trunc
}

// Quantize + edge exchange (2 MIO ops; edge bins recomputed on fma pipe).
__device__ __forceinline__ void build(float4 v, int lane, RowS& R) {
    R.x[1] = v.x; R.x[2] = v.y; R.x[3] = v.z; R.x[4] = v.w;
#pragma unroll
    for (int i = 1; i <= 4; ++i) R.b[i] = quant(R.x[i]);
    R.x[0] = __shfl_up_sync(0xffffffffu, v.w, 1);
    R.x[5] = __shfl_down_sync(0xffffffffu, v.x, 1);
    if (lane == 0)  R.x[0] = 0.f;   // x=0 kills the term; b irrelevant
    if (lane == 31) R.x[5] = 0.f;
    R.b[0] = quant(R.x[0]);
    R.b[5] = quant(R.x[5]);
}

__global__ __launch_bounds__(256, 4)
void col_kernel(const float* __restrict__ x,
                const float* __restrict__ Wp,
                const float* __restrict__ Lp,
                float* __restrict__ out) {
    // Bank-replicated WL table: addr = laneBase + bp*128 + bq*640 + o*3200.
    // Lane l only ever touches bank l -> conflict-free LDS.
    __shared__ float sWL[225 * 32];

    for (int t = threadIdx.x; t < 225 * 32; t += 256) {
        int idx = t >> 5;               // o*25 + bq*5 + bp
        int o  = idx / 25;
        int i  = idx - o * 25;          // bq*5 + bp (L row-major: L[bq][bp])
        sWL[t] = Wp[o] * Lp[i];
    }
    __syncthreads();

    const int lane = threadIdx.x & 31;
    const int gw   = blockIdx.x * 8 + (threadIdx.x >> 5);
    const char* laneBase = reinterpret_cast<const char*>(sWL) + lane * 4;

    // Contiguous global-row strip for this warp.
    long long gs = (long long)gw * TOTROWS / NWARP;
    long long ge = (long long)(gw + 1) * TOTROWS / NWARP;

    long long s = gs;
    while (s < ge) {
        const int p  = (int)(s >> 7);
        const int rs = (int)(s & 127);
        const int re = min(H, rs + (int)(ge - s));     // segment = one plane
        const float* xp = x + (size_t)p * PLANE;
        float* op = out + (size_t)p * PLANE;

        RowS Rr[3];
        float4 wv[3];
        build(ldrow(xp, rs - 1, lane), lane, Rr[0]);
        build(ldrow(xp, rs,     lane), lane, Rr[1]);
        wv[2] = ldrow(xp, rs + 1, lane);

        // 3-row blocks; all rotation indices static. Invariant at block top:
        // Rr[0]=row k-1, Rr[1]=row k, wv[2]=raw row k+1.
        for (int k = rs; k < re; k += 3) {
#pragma unroll
            for (int j = 0; j < 3; ++j) {
                const int r = k + j;
                wv[j] = ldrow(xp, r + 2, lane);            // prefetch
                build(wv[(j + 2) % 3], lane, Rr[(j + 2) % 3]);

                const RowS& A  = Rr[j % 3];
                const RowS& Bc = Rr[(j + 1) % 3];
                const RowS& Cn = Rr[(j + 2) % 3];

                float res[4];
#pragma unroll
                for (int i = 0; i < 4; ++i) {
                    const char* pb = laneBase + Bc.b[i + 1] * 128;
                    float sacc = 0.f;
#define COL_TERM(R, o, dw)                                                     \
                    sacc += *reinterpret_cast<const float*>(                   \
                                pb + (R).b[i + (dw)] * 640 + (o) * 3200)       \
                            * (R).x[i + (dw)];
                    COL_TERM(A,  0, 0) COL_TERM(A,  1, 1) COL_TERM(A,  2, 2)
                    COL_TERM(Bc, 3, 0) COL_TERM(Bc, 4, 1) COL_TERM(Bc, 5, 2)
                    COL_TERM(Cn, 6, 0) COL_TERM(Cn, 7, 1) COL_TERM(Cn, 8, 2)
#undef COL_TERM
                    res[i] = sacc;
                }

                if (j == 0 || r < re)
                    *reinterpret_cast<float4*>(op + r * Wd + lane * 4) =
                        make_float4(res[0], res[1], res[2], res[3]);
            }
        }
        s += re - rs;
    }
}

extern "C" void kernel_launch(void* const* d_in, const int* in_sizes, int n_in,
                              void* d_out, int out_size) {
    const float* x = nullptr;
    const float* W = nullptr;
    const float* L = nullptr;
    for (int i = 0; i < n_in; ++i) {
        if (in_sizes[i] == 9)       W = (const float*)d_in[i];
        else if (in_sizes[i] == 25) L = (const float*)d_in[i];
        else                        x = (const float*)d_in[i];
    }
    col_kernel<<<NBLK, 256>>>(x, W, L, (float*)d_out);
}